// round 13
// baseline (speedup 1.0000x reference)
#include <cuda_runtime.h>
#include <math.h>

// DoublePAN, single persistent kernel, round 13.
// Base = round-11 (25.1us). STRUCTURAL change: the 4 post-union grid
// barriers are replaced by PER-ROW dataflow flags.
//   - flag[row] is monotonic: owner warp bumps it 4x per launch (p ready,
//     t1 ready, q2 ready, t1' ready). base = flag[row] at entry = 4r
//     (stream-ordered launches). Consumers poll only their <=deg neighbors'
//     flags (one lane per neighbor + __all_sync), then __threadfence
//     (acquire + L1 invalidate), then gather. Phases pipeline; no global
//     wait for the slowest block.
//   - writer protocol: stores -> __threadfence (all lanes) -> __syncwarp ->
//     lane0 volatile flag store.
//   - g_bits double-buffered by replay parity pr=(base>>2)&1: this launch
//     uses buffer pr and clears buffer 1-pr (dead: fully read last launch,
//     next written next launch) during phase 0. No clear barrier needed.
//   - ONE grid barrier remains: edges -> union (genuinely global).

#define MAXN 2048
#define MAXNW (MAXN / 32)
#define CAP 128
#define NTHR 256
#define WPB 8

// two parity buffers (2N rows each) + 1 always-zero pad row
__device__ __align__(16) unsigned g_bits[(4 * MAXN + 1) * MAXNW];
__device__ unsigned g_barctr[2];              // monotonic grid barrier ticket
__device__ unsigned g_flag[MAXN];             // per-row phase flags, monotonic
__device__ float    g_p [(MAXN + 1) * 16];    // dinv .* h1 (+ zero pad row)
__device__ float    g_t1[(MAXN + 1) * 32];
__device__ float    g_q2[(MAXN + 1) * 32];

__device__ __forceinline__ void gbar(int idx) {
    __threadfence();
    __syncthreads();
    if (threadIdx.x == 0) {
        unsigned nb = gridDim.x;
        unsigned t = atomicAdd(&g_barctr[idx], 1u);
        unsigned target = t - (t % nb) + nb;
        while ((int)(*(volatile unsigned*)&g_barctr[idx] - target) < 0) { }
        __threadfence();
    }
    __syncthreads();
}

__device__ __forceinline__ int warp_exscan(int v, int lane) {
    int s = v;
    #pragma unroll
    for (int o = 1; o < 32; o <<= 1) {
        int u = __shfl_up_sync(0xffffffffu, s, o);
        if (lane >= o) s += u;
    }
    return s - v;
}

// wait until flag[lst[k]] >= tgt for all k < deg (warp-collective)
__device__ __forceinline__ void wait_flags(const int* lst, int deg,
                                           unsigned tgt, int lane) {
    for (;;) {
        bool ok = true;
        for (int k = lane; k < deg; k += 32) {
            unsigned v = *(volatile unsigned*)&g_flag[lst[k]];
            ok &= (v >= tgt);
        }
        if (__all_sync(0xffffffffu, ok)) break;
    }
    __threadfence();   // acquire: order gathers after flag observation
}

// publish: my stores -> visible gpu-wide -> then flag bump
__device__ __forceinline__ void publish(int row, unsigned val, int lane) {
    __threadfence();
    __syncwarp();
    if (lane == 0) *(volatile unsigned*)&g_flag[row] = val;
}

__global__ void __launch_bounds__(NTHR) k_mega(
    const float* __restrict__ x, const int* __restrict__ ei,
    const float* __restrict__ fw1, const float* __restrict__ w1,
    const float* __restrict__ b1, const float* __restrict__ fw2,
    const float* __restrict__ w2, const float* __restrict__ b2,
    float* __restrict__ out, int N, int E, int F, int nw)
{
    __shared__ __align__(16) float sW[16 * 512];   // W1 [c][f]; aliased as sA
    __shared__ int   sB[WPB][CAP];                 // per-warp padded CSR list
    __shared__ float sW2T[16 * 32];                // W2^T [k][c]
    __shared__ float sH[WPB][16];                  // per-warp h1 broadcast

    const int tid = threadIdx.x, bid = blockIdx.x;
    const int gtid = bid * NTHR + tid;
    const int wb = tid >> 5, lane = tid & 31;
    const int row = bid * WPB + wb;        // grid = N/8 = 256
    const int PADROW = N;                  // zero row in value arrays
    const int PADBIT = 4 * N;              // zero row in bitmask array

    // replay epoch + parity (all flags equal 4r at kernel entry)
    const unsigned base = *(volatile unsigned*)&g_flag[row];
    const int pr = (int)((base >> 2) & 1u);
    const int bb = pr * 2 * N;             // this launch's bits buffer base row

    // ---- phase 0: clear other-parity buffer + edges + preloads + GEMM ----
    {
        int otherQ = (1 - pr) * (2 * N * nw / 4);   // uint4 index
        ((uint4*)g_bits)[otherQ + gtid] = make_uint4(0u, 0u, 0u, 0u);
    }
    if (gtid < E) {
        int s = ei[gtid], t = ei[E + gtid];
        atomicOr(&g_bits[(size_t)(bb + s) * nw + (t >> 5)], 1u << (t & 31));
        atomicOr(&g_bits[(size_t)(bb + N + t) * nw + (s >> 5)], 1u << (s & 31));
    }

    const float f10 = fw1[0], f11 = fw1[1], f12 = fw1[2];
    const float f20 = fw2[0], f21 = fw2[1], f22 = fw2[2];
    const float b2r = b2[lane];
    for (int e = tid; e < 512; e += NTHR) {
        int c = e >> 4, k = e & 15;
        sW2T[k * 32 + c] = w2[e];
    }

    float qv = 0.f;   // own-row h1 channel (lanes < 16)
    {
        for (int e = tid; e < 16 * 512; e += NTHR) sW[e] = w1[e];
        __syncthreads();
        const float4* x4 = (const float4*)(x + (size_t)row * F);
        float4 xv[4];
        #pragma unroll
        for (int i = 0; i < 4; i++) xv[i] = x4[lane + 32 * i];
        const float4* sW4 = (const float4*)sW;
        float acc[16];
        #pragma unroll
        for (int c = 0; c < 16; c++) acc[c] = 0.f;
        #pragma unroll
        for (int c = 0; c < 16; c++) {
            #pragma unroll
            for (int i = 0; i < 4; i++) {
                float4 wv = sW4[c * 128 + lane + 32 * i];
                acc[c] = fmaf(xv[i].x, wv.x, acc[c]);
                acc[c] = fmaf(xv[i].y, wv.y, acc[c]);
                acc[c] = fmaf(xv[i].z, wv.z, acc[c]);
                acc[c] = fmaf(xv[i].w, wv.w, acc[c]);
            }
        }
        #pragma unroll
        for (int c = 0; c < 16; c++) {
            float v = acc[c];
            #pragma unroll
            for (int o = 16; o; o >>= 1) v += __shfl_xor_sync(0xffffffffu, v, o);
            if (lane == c) qv = v;
        }
        if (lane < 16) qv += b1[lane];
    }
    gbar(0);   // the only grid barrier: all edge bits must exist before union

    // ---- union: lists (padded), deg, dinv, p = dinv*q; publish base+1 ----
    float dv;
    int   degB, degPad;
    float pv = 0.f;
    {
        int* sA = (int*)sW;
        const unsigned* arow = &g_bits[(size_t)(bb + row) * nw];
        const unsigned* brow = &g_bits[(size_t)(bb + N + row) * nw];
        int basei = lane * 64;

        unsigned a0 = arow[2 * lane], a1 = arow[2 * lane + 1];
        int tot = __popc(a0) + __popc(a1);
        int off = warp_exscan(tot, lane);
        int degA = __shfl_sync(0xffffffffu, off + tot, 31);
        int pos = off;
        unsigned wt = a0;
        while (wt) { int bbit = __ffs(wt) - 1; wt &= wt - 1; if (pos < CAP) sA[wb * CAP + pos] = bb + basei + bbit; pos++; }
        wt = a1;
        while (wt) { int bbit = __ffs(wt) - 1; wt &= wt - 1; if (pos < CAP) sA[wb * CAP + pos] = bb + basei + 32 + bbit; pos++; }
        if (degA > CAP) degA = CAP;
        int degApad = (degA + 15) & ~15;
        for (int k = degA + lane; k < degApad; k += 32) sA[wb * CAP + k] = PADBIT;

        unsigned b0 = brow[2 * lane], b1v = brow[2 * lane + 1];
        int totB = __popc(b0) + __popc(b1v);
        int offB = warp_exscan(totB, lane);
        degB = __shfl_sync(0xffffffffu, offB + totB, 31);
        int posB = offB;
        wt = b0;
        while (wt) { int bbit = __ffs(wt) - 1; wt &= wt - 1; if (posB < CAP) sB[wb][posB] = basei + bbit; posB++; }
        wt = b1v;
        while (wt) { int bbit = __ffs(wt) - 1; wt &= wt - 1; if (posB < CAP) sB[wb][posB] = basei + 32 + bbit; posB++; }
        if (degB > CAP) degB = CAP;
        degPad = (degB + 31) & ~31;
        if (degPad > CAP) degPad = CAP;
        for (int k = degB + lane; k < degPad; k += 32) sB[wb][k] = PADROW;
        __syncwarp();

        // union: {row} | Arow | OR_{j in Arow} Arow_j  (16/round, padded)
        unsigned acc0 = arow[lane];
        unsigned acc1 = arow[lane + 32];
        int wi = row >> 5; unsigned ib = 1u << (row & 31);
        if (lane == wi)           acc0 |= ib;
        else if (lane + 32 == wi) acc1 |= ib;
        for (int k = 0; k < degApad; k += 16) {
            #pragma unroll
            for (int u = 0; u < 16; u++) {
                const unsigned* r = &g_bits[(size_t)sA[wb * CAP + k + u] * nw];
                acc0 |= r[lane];
                acc1 |= r[lane + 32];
            }
        }
        int cnt = __popc(acc0) + __popc(acc1);
        cnt = __reduce_add_sync(0xffffffffu, cnt);
        dv = rsqrtf((float)cnt);
        if (lane < 16) {
            pv = dv * qv;
            g_p[row * 16 + lane] = pv;
        }
    }
    publish(row, base + 1u, lane);

    const int half = lane >> 4, ch = lane & 15;

    // ---- spmm16: wait neighbors' p; t1 = B p; publish base+2 ----
    float t1own;
    {
        wait_flags(sB[wb], degB, base + 1u, lane);
        float acc = 0.f;
        for (int k = 0; k < degPad; k += 32) {
            float a0 = 0.f, a1 = 0.f, a2 = 0.f, a3 = 0.f;
            #pragma unroll
            for (int u = 0; u < 4; u++) {
                a0 += g_p[sB[wb][k +      2*u + half] * 16 + ch];
                a1 += g_p[sB[wb][k +  8 + 2*u + half] * 16 + ch];
                a2 += g_p[sB[wb][k + 16 + 2*u + half] * 16 + ch];
                a3 += g_p[sB[wb][k + 24 + 2*u + half] * 16 + ch];
            }
            acc += (a0 + a1) + (a2 + a3);
        }
        acc += __shfl_down_sync(0xffffffffu, acc, 16);
        t1own = acc;
        if (lane < 16) g_t1[row * 16 + lane] = acc;
    }
    publish(row, base + 2u, lane);

    // ---- l1post: wait neighbors' t1; t2=B t1; h1; q2; publish base+3 ----
    float q2own;
    {
        wait_flags(sB[wb], degB, base + 2u, lane);
        float t2 = 0.f;
        for (int k = 0; k < degPad; k += 32) {
            float a0 = 0.f, a1 = 0.f, a2 = 0.f, a3 = 0.f;
            #pragma unroll
            for (int u = 0; u < 4; u++) {
                a0 += g_t1[sB[wb][k +      2*u + half] * 16 + ch];
                a1 += g_t1[sB[wb][k +  8 + 2*u + half] * 16 + ch];
                a2 += g_t1[sB[wb][k + 16 + 2*u + half] * 16 + ch];
                a3 += g_t1[sB[wb][k + 24 + 2*u + half] * 16 + ch];
            }
            t2 += (a0 + a1) + (a2 + a3);
        }
        t2 += __shfl_down_sync(0xffffffffu, t2, 16);

        if (lane < 16) {
            float r = f10 * pv + f11 * t1own + f12 * t2;
            sH[wb][lane] = fmaxf(dv * r, 0.f);
        }
        __syncwarp();
        float acc = b2r;
        #pragma unroll
        for (int k2 = 0; k2 < 16; k2++)
            acc = fmaf(sW2T[k2 * 32 + lane], sH[wb][k2], acc);
        q2own = dv * acc;
        g_q2[row * 32 + lane] = q2own;
    }
    publish(row, base + 3u, lane);

    // ---- spmm32: wait neighbors' q2; t1' = B q2; publish base+4 ----
    float t132;
    {
        wait_flags(sB[wb], degB, base + 3u, lane);
        float acc = 0.f;
        for (int k = 0; k < degPad; k += 32) {
            float a0 = 0.f, a1 = 0.f, a2 = 0.f, a3 = 0.f;
            #pragma unroll
            for (int u = 0; u < 8; u++) {
                a0 += g_q2[sB[wb][k      + u] * 32 + lane];
                a1 += g_q2[sB[wb][k +  8 + u] * 32 + lane];
                a2 += g_q2[sB[wb][k + 16 + u] * 32 + lane];
                a3 += g_q2[sB[wb][k + 24 + u] * 32 + lane];
            }
            acc += (a0 + a1) + (a2 + a3);
        }
        t132 = acc;
        g_t1[row * 32 + lane] = acc;
    }
    publish(row, base + 4u, lane);

    // ---- l2post: wait neighbors' t1'; z; log_softmax -> out ----
    {
        wait_flags(sB[wb], degB, base + 4u, lane);
        float t2 = 0.f;
        for (int k = 0; k < degPad; k += 32) {
            float a0 = 0.f, a1 = 0.f, a2 = 0.f, a3 = 0.f;
            #pragma unroll
            for (int u = 0; u < 8; u++) {
                a0 += g_t1[sB[wb][k      + u] * 32 + lane];
                a1 += g_t1[sB[wb][k +  8 + u] * 32 + lane];
                a2 += g_t1[sB[wb][k + 16 + u] * 32 + lane];
                a3 += g_t1[sB[wb][k + 24 + u] * 32 + lane];
            }
            t2 += (a0 + a1) + (a2 + a3);
        }

        float z = dv * (f20 * q2own + f21 * t132 + f22 * t2);
        float m = z;
        #pragma unroll
        for (int o = 16; o; o >>= 1) m = fmaxf(m, __shfl_xor_sync(0xffffffffu, m, o));
        float e = __expf(z - m);
        float s = e;
        #pragma unroll
        for (int o = 16; o; o >>= 1) s += __shfl_xor_sync(0xffffffffu, s, o);
        out[row * 32 + lane] = z - m - logf(s);
    }
}

extern "C" void kernel_launch(void* const* d_in, const int* in_sizes, int n_in,
                              void* d_out, int out_size) {
    const float* x   = (const float*)d_in[0];
    const int*   ei  = (const int*)  d_in[1];
    const float* fw1 = (const float*)d_in[2];
    const float* w1  = (const float*)d_in[3];
    const float* b1  = (const float*)d_in[4];
    const float* fw2 = (const float*)d_in[5];
    const float* w2  = (const float*)d_in[6];
    const float* b2  = (const float*)d_in[7];
    float* out = (float*)d_out;

    int H = in_sizes[4];            // 16
    int F = in_sizes[3] / H;        // 512
    int N = in_sizes[0] / F;        // 2048
    int E = in_sizes[1] / 2;        // 32768
    int nw = (N + 31) / 32;         // 64

    int grid = N / WPB;             // 256 blocks; grid*NTHR uint4 = 1MB clear
    k_mega<<<grid, NTHR>>>(x, ei, fw1, w1, b1, fw2, w2, b2, out, N, E, F, nw);
}

// round 14
// speedup vs baseline: 2.1471x; 2.1471x over previous
#include <cuda_runtime.h>
#include <math.h>

// DoublePAN, single persistent kernel, round 14.
// Base = round-11 EXACTLY (25.1us best; dataflow-flag R13 reverted — per-warp
// fence+poll cost >> 5 central barriers). Changes vs R11:
//  - GEMM channel reduction: butterfly transpose-reduce (16 shfl + fold)
//    instead of 16x full 5-shfl reductions (80 shfl) — shortens phase 0,
//    which gates the single slowest block before gbar0.
//  - x row loaded BEFORE W1 smem staging (LDG overlaps STS).
//  - layer-2 B*q2 goes to a separate g_t2 buffer (first-touch purity; no
//    L1 aliasing with the width-16 g_t1 lines read in l1post).

#define MAXN 2048
#define MAXNW (MAXN / 32)
#define CAP 128
#define NTHR 256
#define WPB 8

// +1 padding row each (never written; statically zero, stays zero)
__device__ __align__(16) unsigned g_bits[(2 * MAXN + 1) * MAXNW];
__device__ unsigned g_barctr[8];              // monotonic, never reset
__device__ float    g_p [(MAXN + 1) * 16];    // dinv .* h1
__device__ float    g_t1[(MAXN + 1) * 32];
__device__ float    g_t2[(MAXN + 1) * 32];    // layer-2 B*q2
__device__ float    g_q2[(MAXN + 1) * 32];

__device__ __forceinline__ void gbar(int idx) {
    __threadfence();
    __syncthreads();
    if (threadIdx.x == 0) {
        unsigned nb = gridDim.x;
        unsigned t = atomicAdd(&g_barctr[idx], 1u);
        unsigned target = t - (t % nb) + nb;
        while ((int)(*(volatile unsigned*)&g_barctr[idx] - target) < 0) { }
        __threadfence();
    }
    __syncthreads();
}

__device__ __forceinline__ int warp_exscan(int v, int lane) {
    int s = v;
    #pragma unroll
    for (int o = 1; o < 32; o <<= 1) {
        int u = __shfl_up_sync(0xffffffffu, s, o);
        if (lane >= o) s += u;
    }
    return s - v;
}

__global__ void __launch_bounds__(NTHR) k_mega(
    const float* __restrict__ x, const int* __restrict__ ei,
    const float* __restrict__ fw1, const float* __restrict__ w1,
    const float* __restrict__ b1, const float* __restrict__ fw2,
    const float* __restrict__ w2, const float* __restrict__ b2,
    float* __restrict__ out, int N, int E, int F, int nw)
{
    __shared__ __align__(16) float sW[16 * 512];   // W1 [c][f]; aliased as sA
    __shared__ int   sB[WPB][CAP];                 // per-warp padded CSR list
    __shared__ float sW2T[16 * 32];                // W2^T [k][c]
    __shared__ float sH[WPB][16];                  // per-warp h1 broadcast

    const int tid = threadIdx.x, bid = blockIdx.x;
    const int gtid = bid * NTHR + tid;
    const int wb = tid >> 5, lane = tid & 31;
    const int row = bid * WPB + wb;        // grid = N/8 = 256
    const int PADROW = N;                  // zero row in value arrays
    const int PADBIT = 2 * N;              // zero row in bitmask array

    // ---- phase 0: edges + constant preloads + GEMM ----
    // x row loads issued FIRST (overlap with atomics + smem staging)
    float4 xv[4];
    {
        const float4* x4 = (const float4*)(x + (size_t)row * F);
        #pragma unroll
        for (int i = 0; i < 4; i++) xv[i] = x4[lane + 32 * i];
    }
    if (gtid < E) {
        int s = ei[gtid], t = ei[E + gtid];
        atomicOr(&g_bits[s * nw + (t >> 5)], 1u << (t & 31));
        atomicOr(&g_bits[(N + t) * nw + (s >> 5)], 1u << (s & 31));
    }

    const float f10 = fw1[0], f11 = fw1[1], f12 = fw1[2];
    const float f20 = fw2[0], f21 = fw2[1], f22 = fw2[2];
    const float b2r = b2[lane];
    for (int e = tid; e < 512; e += NTHR) {
        int c = e >> 4, k = e & 15;
        sW2T[k * 32 + c] = w2[e];
    }

    float qv = 0.f;   // own-row h1 channel (lanes < 16)
    {
        for (int e = tid; e < 16 * 512; e += NTHR) sW[e] = w1[e];
        __syncthreads();
        const float4* sW4 = (const float4*)sW;
        float v[16];
        #pragma unroll
        for (int c = 0; c < 16; c++) v[c] = 0.f;
        #pragma unroll
        for (int c = 0; c < 16; c++) {
            #pragma unroll
            for (int i = 0; i < 4; i++) {
                float4 wv = sW4[c * 128 + lane + 32 * i];
                v[c] = fmaf(xv[i].x, wv.x, v[c]);
                v[c] = fmaf(xv[i].y, wv.y, v[c]);
                v[c] = fmaf(xv[i].z, wv.z, v[c]);
                v[c] = fmaf(xv[i].w, wv.w, v[c]);
            }
        }
        // butterfly transpose-reduce: after 4 steps lane holds channel
        // (lane & 15) summed over its 16-lane group; fold x^16 completes.
        #pragma unroll
        for (int step = 0; step < 4; step++) {
            int mask = 1 << step;
            #pragma unroll
            for (int j = 0; j < (16 >> (step + 1)); j++) {
                float a = (lane & mask) ? v[2 * j] : v[2 * j + 1];
                float b = __shfl_xor_sync(0xffffffffu, a, mask);
                v[j] = ((lane & mask) ? v[2 * j + 1] : v[2 * j]) + b;
            }
        }
        v[0] += __shfl_xor_sync(0xffffffffu, v[0], 16);
        if (lane < 16) qv = v[0] + b1[lane];
    }
    gbar(0);

    // ---- union: lists (padded), deg, dinv, p = dinv*q ----
    float dv;
    int   degPad;      // padded B-list length (multiple of 32)
    float pv = 0.f;
    {
        int* sA = (int*)sW;
        const unsigned* arow = &g_bits[row * nw];
        const unsigned* brow = &g_bits[(size_t)(N + row) * nw];
        int base = lane * 64;

        unsigned a0 = arow[2 * lane], a1 = arow[2 * lane + 1];
        int tot = __popc(a0) + __popc(a1);
        int off = warp_exscan(tot, lane);
        int degA = __shfl_sync(0xffffffffu, off + tot, 31);
        int pos = off;
        unsigned wt = a0;
        while (wt) { int bb = __ffs(wt) - 1; wt &= wt - 1; if (pos < CAP) sA[wb * CAP + pos] = base + bb; pos++; }
        wt = a1;
        while (wt) { int bb = __ffs(wt) - 1; wt &= wt - 1; if (pos < CAP) sA[wb * CAP + pos] = base + 32 + bb; pos++; }
        if (degA > CAP) degA = CAP;
        int degApad = (degA + 15) & ~15;
        for (int k = degA + lane; k < degApad; k += 32) sA[wb * CAP + k] = PADBIT;

        unsigned b0 = brow[2 * lane], b1v = brow[2 * lane + 1];
        int totB = __popc(b0) + __popc(b1v);
        int offB = warp_exscan(totB, lane);
        int degB = __shfl_sync(0xffffffffu, offB + totB, 31);
        int posB = offB;
        wt = b0;
        while (wt) { int bb = __ffs(wt) - 1; wt &= wt - 1; if (posB < CAP) sB[wb][posB] = base + bb; posB++; }
        wt = b1v;
        while (wt) { int bb = __ffs(wt) - 1; wt &= wt - 1; if (posB < CAP) sB[wb][posB] = base + 32 + bb; posB++; }
        if (degB > CAP) degB = CAP;
        degPad = (degB + 31) & ~31;
        if (degPad > CAP) degPad = CAP;
        for (int k = degB + lane; k < degPad; k += 32) sB[wb][k] = PADROW;
        __syncwarp();

        // union: {row} | Arow | OR_{j in Arow} Arow_j  (16/round, padded)
        unsigned acc0 = arow[lane];
        unsigned acc1 = arow[lane + 32];
        int wi = row >> 5; unsigned ib = 1u << (row & 31);
        if (lane == wi)           acc0 |= ib;
        else if (lane + 32 == wi) acc1 |= ib;
        for (int k = 0; k < degApad; k += 16) {
            #pragma unroll
            for (int u = 0; u < 16; u++) {
                const unsigned* r = &g_bits[(size_t)sA[wb * CAP + k + u] * nw];
                acc0 |= r[lane];
                acc1 |= r[lane + 32];
            }
        }
        int cnt = __popc(acc0) + __popc(acc1);
        cnt = __reduce_add_sync(0xffffffffu, cnt);
        dv = rsqrtf((float)cnt);
        if (lane < 16) {
            pv = dv * qv;
            g_p[row * 16 + lane] = pv;
        }
    }
    gbar(1);

    // ---- restore invariant early (last g_bits read was union phase) ----
    ((uint4*)g_bits)[gtid] = make_uint4(0u, 0u, 0u, 0u);

    const int half = lane >> 4, ch = lane & 15;

    // ---- spmm16: t1 = B p  (dual-lane, 32 slots/round, branch-free) ----
    float t1own;
    {
        float acc = 0.f;
        for (int k = 0; k < degPad; k += 32) {
            float a0 = 0.f, a1 = 0.f, a2 = 0.f, a3 = 0.f;
            #pragma unroll
            for (int u = 0; u < 4; u++) {
                a0 += g_p[sB[wb][k +      2*u + half] * 16 + ch];
                a1 += g_p[sB[wb][k +  8 + 2*u + half] * 16 + ch];
                a2 += g_p[sB[wb][k + 16 + 2*u + half] * 16 + ch];
                a3 += g_p[sB[wb][k + 24 + 2*u + half] * 16 + ch];
            }
            acc += (a0 + a1) + (a2 + a3);
        }
        acc += __shfl_down_sync(0xffffffffu, acc, 16);
        t1own = acc;
        if (lane < 16) g_t1[row * 16 + lane] = acc;
    }
    gbar(2);

    // ---- l1post: t2=B t1; h=relu(d*(f0*p+f1*t1+f2*t2)); q2=d*(W2 h + b2) ----
    float q2own;
    {
        float t2 = 0.f;
        for (int k = 0; k < degPad; k += 32) {
            float a0 = 0.f, a1 = 0.f, a2 = 0.f, a3 = 0.f;
            #pragma unroll
            for (int u = 0; u < 4; u++) {
                a0 += g_t1[sB[wb][k +      2*u + half] * 16 + ch];
                a1 += g_t1[sB[wb][k +  8 + 2*u + half] * 16 + ch];
                a2 += g_t1[sB[wb][k + 16 + 2*u + half] * 16 + ch];
                a3 += g_t1[sB[wb][k + 24 + 2*u + half] * 16 + ch];
            }
            t2 += (a0 + a1) + (a2 + a3);
        }
        t2 += __shfl_down_sync(0xffffffffu, t2, 16);

        if (lane < 16) {
            float r = f10 * pv + f11 * t1own + f12 * t2;
            sH[wb][lane] = fmaxf(dv * r, 0.f);
        }
        __syncwarp();
        float acc = b2r;
        #pragma unroll
        for (int k2 = 0; k2 < 16; k2++)
            acc = fmaf(sW2T[k2 * 32 + lane], sH[wb][k2], acc);
        q2own = dv * acc;
        g_q2[row * 32 + lane] = q2own;
    }
    gbar(3);

    // ---- spmm32: t2buf = B q2  (32 neighbors/round, branch-free) ----
    float t132;
    {
        float acc = 0.f;
        for (int k = 0; k < degPad; k += 32) {
            float a0 = 0.f, a1 = 0.f, a2 = 0.f, a3 = 0.f;
            #pragma unroll
            for (int u = 0; u < 8; u++) {
                a0 += g_q2[sB[wb][k      + u] * 32 + lane];
                a1 += g_q2[sB[wb][k +  8 + u] * 32 + lane];
                a2 += g_q2[sB[wb][k + 16 + u] * 32 + lane];
                a3 += g_q2[sB[wb][k + 24 + u] * 32 + lane];
            }
            acc += (a0 + a1) + (a2 + a3);
        }
        t132 = acc;
        g_t2[row * 32 + lane] = acc;
    }
    gbar(4);

    // ---- l2post: t2=B t2buf; z=d*(f0*q2+f1*t1'+f2*t2); log_softmax -> out ----
    {
        float t2 = 0.f;
        for (int k = 0; k < degPad; k += 32) {
            float a0 = 0.f, a1 = 0.f, a2 = 0.f, a3 = 0.f;
            #pragma unroll
            for (int u = 0; u < 8; u++) {
                a0 += g_t2[sB[wb][k      + u] * 32 + lane];
                a1 += g_t2[sB[wb][k +  8 + u] * 32 + lane];
                a2 += g_t2[sB[wb][k + 16 + u] * 32 + lane];
                a3 += g_t2[sB[wb][k + 24 + u] * 32 + lane];
            }
            t2 += (a0 + a1) + (a2 + a3);
        }

        float z = dv * (f20 * q2own + f21 * t132 + f22 * t2);
        float m = z;
        #pragma unroll
        for (int o = 16; o; o >>= 1) m = fmaxf(m, __shfl_xor_sync(0xffffffffu, m, o));
        float e = __expf(z - m);
        float s = e;
        #pragma unroll
        for (int o = 16; o; o >>= 1) s += __shfl_xor_sync(0xffffffffu, s, o);
        out[row * 32 + lane] = z - m - logf(s);
    }
}

extern "C" void kernel_launch(void* const* d_in, const int* in_sizes, int n_in,
                              void* d_out, int out_size) {
    const float* x   = (const float*)d_in[0];
    const int*   ei  = (const int*)  d_in[1];
    const float* fw1 = (const float*)d_in[2];
    const float* w1  = (const float*)d_in[3];
    const float* b1  = (const float*)d_in[4];
    const float* fw2 = (const float*)d_in[5];
    const float* w2  = (const float*)d_in[6];
    const float* b2  = (const float*)d_in[7];
    float* out = (float*)d_out;

    int H = in_sizes[4];            // 16
    int F = in_sizes[3] / H;        // 512
    int N = in_sizes[0] / F;        // 2048
    int E = in_sizes[1] / 2;        // 32768
    int nw = (N + 31) / 32;         // 64

    int grid = N / WPB;             // 256 blocks
    k_mega<<<grid, NTHR>>>(x, ei, fw1, w1, b1, fw2, w2, b2, out, N, E, F, nw);
}